// round 8
// baseline (speedup 1.0000x reference)
#include <cuda_runtime.h>
#include <math.h>
#include <stdint.h>

#define BB   8
#define NN   20000
#define FEAT 256
#define HD   512
#define CATK 4096
#define F1   1024
#define NCHUNK 313

// int8 GEMM smem: CTA 128x64, k-chunk 64, pitch 80
#define IP    80
#define SA0   0
#define SA1   10240
#define SB0   20480
#define SB1   25600
#define ISTG  30720
#define IDYN  (2 * ISTG)

// ---------------- scratch ----------------
__device__ float  d_hf[BB * NN * HD];
__device__ int8_t d_xq0[BB * NN * FEAT];
__device__ int8_t d_xq1[BB * NN * FEAT];
__device__ int8_t d_h1q0[BB * NN * HD];
__device__ int8_t d_h1q1[BB * NN * HD];
__device__ int8_t d_h2q0[BB * NN * HD];
__device__ int8_t d_h2q1[BB * NN * HD];
__device__ int8_t d_w1q0[BB * HD * FEAT];
__device__ int8_t d_w1q1[BB * HD * FEAT];
__device__ int8_t d_w2q0[BB * HD * HD];
__device__ int8_t d_w2q1[BB * HD * HD];
__device__ int8_t d_wfq0[F1 * CATK];
__device__ int8_t d_wfq1[F1 * CATK];
__device__ float  d_sxa[BB * NN];
__device__ float  d_sh1[BB * NN];
__device__ float  d_s3[NN];
__device__ float  d_pmax[BB * NN];
__device__ float  d_sw1[BB * HD];
__device__ float  d_sw2[BB * HD];
__device__ float  d_swf[F1];
__device__ float  d_pw[8 * BB * F1];
__device__ float  d_f [NN * F1];
__device__ float  d_f2[NN * 32];
__device__ float  d_ps[BB * NCHUNK * HD];
__device__ float  d_pq[BB * NCHUNK * HD];
__device__ float  d_scale[BB * HD];
__device__ float  d_shift[BB * HD];
__device__ float  d_wall[F1 * 9 * 32];

// ---------------- helpers ----------------
__device__ __forceinline__ void q2(float v, float inv, int& a0, int& a1) {
    float u  = v * inv;                      // |u| <= 16256
    float f0 = rintf(u * 0.0078125f);        // u/128
    a0 = (int)f0;
    float r  = u - 128.0f * f0;              // [-64, 64]
    a1 = (int)rintf(r * 1.984375f);          // * 127/64
}

__device__ __forceinline__ void cpa16s(uint32_t saddr, const void* g) {
    asm volatile("cp.async.cg.shared.global [%0], [%1], 16;" :: "r"(saddr), "l"(g));
}
__device__ __forceinline__ void cpacommit() {
    asm volatile("cp.async.commit_group;" ::: "memory");
}

__device__ __forceinline__ void imma(int (&d)[4], const uint32_t (&a)[4],
                                     uint32_t b0, uint32_t b1) {
    asm volatile(
        "mma.sync.aligned.m16n8k32.row.col.s32.s8.s8.s32 "
        "{%0,%1,%2,%3}, {%4,%5,%6,%7}, {%8,%9}, {%0,%1,%2,%3};\n"
        : "+r"(d[0]), "+r"(d[1]), "+r"(d[2]), "+r"(d[3])
        : "r"(a[0]), "r"(a[1]), "r"(a[2]), "r"(a[3]), "r"(b0), "r"(b1));
}

// =================================================================
// weight quant: per-output-column max over K, transpose, 2-level quantize
// =================================================================
__global__ __launch_bounds__(256) void wmax_part(
    const float* __restrict__ W, float* __restrict__ pw, int K, int N)
{
    int b = blockIdx.y, z = blockIdx.z;
    int n = blockIdx.x * 256 + threadIdx.x;
    const float* Wb = W + (size_t)b * K * N;
    int kseg = K / 8, k0 = z * kseg;
    float m = 0.f;
    for (int k = k0; k < k0 + kseg; k++)
        m = fmaxf(m, fabsf(Wb[(size_t)k * N + n]));
    pw[((size_t)z * gridDim.y + b) * N + n] = m;
}

__global__ __launch_bounds__(256) void wmax_red(
    const float* __restrict__ pw, float* __restrict__ sw, int BN)
{
    int i = blockIdx.x * 256 + threadIdx.x;
    if (i >= BN) return;
    float m = 0.f;
#pragma unroll
    for (int z = 0; z < 8; z++) m = fmaxf(m, pw[(size_t)z * BN + i]);
    sw[i] = fmaxf(m, 1e-20f) * (1.0f / 16256.0f);
}

__global__ __launch_bounds__(256) void tquant(
    const float* __restrict__ W, const float* __restrict__ sw,
    int8_t* __restrict__ q0, int8_t* __restrict__ q1, int K, int N)
{
    __shared__ float tb[32][33];
    int b = blockIdx.z;
    W  += (size_t)b * K * N;
    q0 += (size_t)b * N * K;
    q1 += (size_t)b * N * K;
    sw += (size_t)b * N;
    int n0 = blockIdx.x * 32, k0 = blockIdx.y * 32;
    int tx = threadIdx.x & 31, ty = threadIdx.x >> 5;
#pragma unroll
    for (int i = 0; i < 4; i++)
        tb[ty + i * 8][tx] = W[(size_t)(k0 + ty + i * 8) * N + n0 + tx];
    __syncthreads();
#pragma unroll
    for (int i = 0; i < 4; i++) {
        int n = n0 + ty + i * 8;
        float inv = 1.0f / sw[n];
        int a0, a1;
        q2(tb[tx][ty + i * 8], inv, a0, a1);
        size_t o = (size_t)n * K + k0 + tx;
        q0[o] = (int8_t)a0;
        q1[o] = (int8_t)a1;
    }
}

// =================================================================
// x quant: one warp per row of 256
// =================================================================
__global__ __launch_bounds__(256) void xquant(
    const float* __restrict__ x, int8_t* __restrict__ q0,
    int8_t* __restrict__ q1, float* __restrict__ sa)
{
    int wg = blockIdx.x * 8 + (threadIdx.x >> 5);
    int lane = threadIdx.x & 31;
    const float* row = x + (size_t)wg * FEAT + lane * 8;
    float4 v0 = *(const float4*)row;
    float4 v1 = *(const float4*)(row + 4);
    float vals[8] = {v0.x, v0.y, v0.z, v0.w, v1.x, v1.y, v1.z, v1.w};
    float m = 0.f;
#pragma unroll
    for (int i = 0; i < 8; i++) m = fmaxf(m, fabsf(vals[i]));
#pragma unroll
    for (int off = 16; off >= 1; off >>= 1)
        m = fmaxf(m, __shfl_xor_sync(0xFFFFFFFFu, m, off));
    float s = fmaxf(m, 1e-20f) * (1.0f / 16256.0f);
    if (lane == 0) sa[wg] = s;
    float inv = 1.0f / s;
    int a0[8], a1[8];
#pragma unroll
    for (int i = 0; i < 8; i++) q2(vals[i], inv, a0[i], a1[i]);
    size_t o = (size_t)wg * FEAT + lane * 8;
    *(char4*)(q0 + o)     = make_char4(a0[0], a0[1], a0[2], a0[3]);
    *(char4*)(q0 + o + 4) = make_char4(a0[4], a0[5], a0[6], a0[7]);
    *(char4*)(q1 + o)     = make_char4(a1[0], a1[1], a1[2], a1[3]);
    *(char4*)(q1 + o + 4) = make_char4(a1[4], a1[5], a1[6], a1[7]);
}

// =================================================================
// int8 2-level GEMM. CTA 128x64, 256 threads (8 warps 2x2, warp 32x32),
// k-chunk 64, 2-stage cp.async.
// C = sA*sB*(16384*G0 + (8192/127)*G1 + (4096/16129)*G2) + bias
// =================================================================
template<bool CAT, bool RELU>
__global__ __launch_bounds__(256, 1) void gemm_i8(
    const int8_t* __restrict__ A0, const int8_t* __restrict__ A1,
    const float* __restrict__ saA,
    const int8_t* __restrict__ B0, const int8_t* __restrict__ B1,
    const float* __restrict__ sbB,
    const float* __restrict__ bias, float* __restrict__ C,
    int M, int N, int K)
{
    extern __shared__ __align__(16) char ism[];
    const uint32_t sbase = (uint32_t)__cvta_generic_to_shared(ism);

    int b = blockIdx.z;
    if (!CAT) {
        A0 += (size_t)b * M * K;
        A1 += (size_t)b * M * K;
        saA += (size_t)b * M;
    }
    B0  += (size_t)b * N * K;
    B1  += (size_t)b * N * K;
    sbB += (size_t)b * N;
    bias += (size_t)b * N;
    C   += (size_t)b * M * N;

    const int tid = threadIdx.x;
    const int m0 = blockIdx.y * 128, n0 = blockIdx.x * 64;
    const int wid = tid >> 5, lane = tid & 31;
    const int wm = (wid >> 1) * 32, wn = (wid & 1) * 32;
    const int g = lane >> 2, tg = lane & 3;

    int G0[2][4][4], G1[2][4][4], G2[2][4][4];
#pragma unroll
    for (int mt = 0; mt < 2; mt++)
#pragma unroll
        for (int nt = 0; nt < 4; nt++)
#pragma unroll
            for (int i = 0; i < 4; i++) {
                G0[mt][nt][i] = 0; G1[mt][nt][i] = 0; G2[mt][nt][i] = 0;
            }

    const int lr = tid >> 2;             // 0..63
    const int sg = (tid & 3) * 16;       // 0..48
    const int arA = min(m0 + lr, M - 1);
    const int arB = min(m0 + lr + 64, M - 1);
    const int brw = n0 + lr;

    const int nk = K >> 6;

    auto load_stage = [&](int stg, int k0) {
        uint32_t st = sbase + stg * ISTG;
        size_t oA0, oA1;
        if (CAT) {
            size_t base = (size_t)(k0 >> 9) * M;
            oA0 = (base + arA) * 512 + (k0 & 511) + sg;
            oA1 = (base + arB) * 512 + (k0 & 511) + sg;
        } else {
            oA0 = (size_t)arA * K + k0 + sg;
            oA1 = (size_t)arB * K + k0 + sg;
        }
        cpa16s(st + SA0 + lr * IP + sg,        A0 + oA0);
        cpa16s(st + SA1 + lr * IP + sg,        A1 + oA0);
        cpa16s(st + SA0 + (lr + 64) * IP + sg, A0 + oA1);
        cpa16s(st + SA1 + (lr + 64) * IP + sg, A1 + oA1);
        size_t oB = (size_t)brw * K + k0 + sg;
        cpa16s(st + SB0 + lr * IP + sg, B0 + oB);
        cpa16s(st + SB1 + lr * IP + sg, B1 + oB);
        cpacommit();
    };

    load_stage(0, 0);

    for (int it = 0; it < nk; it++) {
        if (it + 1 < nk) {
            load_stage((it + 1) & 1, (it + 1) * 64);
            asm volatile("cp.async.wait_group 1;" ::: "memory");
        } else {
            asm volatile("cp.async.wait_group 0;" ::: "memory");
        }
        __syncthreads();

        const char* stp = ism + (it & 1) * ISTG;
        const char* pA0 = stp + SA0;
        const char* pA1 = stp + SA1;
        const char* pB0 = stp + SB0;
        const char* pB1 = stp + SB1;

#pragma unroll
        for (int ks = 0; ks < 2; ks++) {
            uint32_t bf0[4][2], bf1[4][2];
#pragma unroll
            for (int nt = 0; nt < 4; nt++) {
                int ad = (wn + nt * 8 + g) * IP + ks * 32 + tg * 4;
                bf0[nt][0] = *(const uint32_t*)(pB0 + ad);
                bf0[nt][1] = *(const uint32_t*)(pB0 + ad + 16);
                bf1[nt][0] = *(const uint32_t*)(pB1 + ad);
                bf1[nt][1] = *(const uint32_t*)(pB1 + ad + 16);
            }
#pragma unroll
            for (int mt = 0; mt < 2; mt++) {
                int ad = (wm + mt * 16 + g) * IP + ks * 32 + tg * 4;
                uint32_t aA[4], aB[4];
                aA[0] = *(const uint32_t*)(pA0 + ad);
                aA[1] = *(const uint32_t*)(pA0 + ad + 8 * IP);
                aA[2] = *(const uint32_t*)(pA0 + ad + 16);
                aA[3] = *(const uint32_t*)(pA0 + ad + 8 * IP + 16);
                aB[0] = *(const uint32_t*)(pA1 + ad);
                aB[1] = *(const uint32_t*)(pA1 + ad + 8 * IP);
                aB[2] = *(const uint32_t*)(pA1 + ad + 16);
                aB[3] = *(const uint32_t*)(pA1 + ad + 8 * IP + 16);
#pragma unroll
                for (int nt = 0; nt < 4; nt++) {
                    imma(G0[mt][nt], aA, bf0[nt][0], bf0[nt][1]);
                    imma(G1[mt][nt], aA, bf1[nt][0], bf1[nt][1]);
                    imma(G1[mt][nt], aB, bf0[nt][0], bf0[nt][1]);
                    imma(G2[mt][nt], aB, bf1[nt][0], bf1[nt][1]);
                }
            }
        }
        __syncthreads();
    }

    const float C1c = 8192.0f / 127.0f;
    const float C2c = 4096.0f / 16129.0f;
#pragma unroll
    for (int mt = 0; mt < 2; mt++) {
        int r0 = m0 + wm + mt * 16 + g;
#pragma unroll
        for (int nt = 0; nt < 4; nt++) {
            int c = n0 + wn + nt * 8 + 2 * tg;
            float sc0 = sbB[c], sc1 = sbB[c + 1];
            float bi0 = bias[c], bi1 = bias[c + 1];
            if (r0 < M) {
                float sr = saA[r0];
                float v0 = sr * sc0 * (16384.0f * (float)G0[mt][nt][0]
                          + C1c * (float)G1[mt][nt][0] + C2c * (float)G2[mt][nt][0]) + bi0;
                float v1 = sr * sc1 * (16384.0f * (float)G0[mt][nt][1]
                          + C1c * (float)G1[mt][nt][1] + C2c * (float)G2[mt][nt][1]) + bi1;
                if (RELU) { v0 = fmaxf(v0, 0.f); v1 = fmaxf(v1, 0.f); }
                *(float2*)&C[(size_t)r0 * N + c] = make_float2(v0, v1);
            }
            if (r0 + 8 < M) {
                float sr = saA[r0 + 8];
                float v2 = sr * sc0 * (16384.0f * (float)G0[mt][nt][2]
                          + C1c * (float)G1[mt][nt][2] + C2c * (float)G2[mt][nt][2]) + bi0;
                float v3 = sr * sc1 * (16384.0f * (float)G0[mt][nt][3]
                          + C1c * (float)G1[mt][nt][3] + C2c * (float)G2[mt][nt][3]) + bi1;
                if (RELU) { v2 = fmaxf(v2, 0.f); v3 = fmaxf(v3, 0.f); }
                *(float2*)&C[(size_t)(r0 + 8) * N + c] = make_float2(v2, v3);
            }
        }
    }
}

// =================================================================
// BatchNorm stats (two-pass deterministic)
// =================================================================
__global__ __launch_bounds__(256) void bn_partial(
    const float* __restrict__ h, float* __restrict__ ps, float* __restrict__ pq)
{
    int chunk = blockIdx.x;
    int b     = blockIdx.y;
    int tid   = threadIdx.x;
    int n0    = chunk * 64;
    int rows  = min(64, NN - n0);
    const float* base = h + ((size_t)b * NN + n0) * HD;
    float s0 = 0.f, q0 = 0.f, s1 = 0.f, q1 = 0.f;
    for (int r = 0; r < rows; r++) {
        float v0 = base[(size_t)r * HD + tid];
        float v1 = base[(size_t)r * HD + tid + 256];
        s0 += v0; q0 += v0 * v0;
        s1 += v1; q1 += v1 * v1;
    }
    size_t o = ((size_t)b * NCHUNK + chunk) * HD;
    ps[o + tid]       = s0;
    ps[o + tid + 256] = s1;
    pq[o + tid]       = q0;
    pq[o + tid + 256] = q1;
}

__global__ __launch_bounds__(512) void bn_finalize(
    const float* __restrict__ ps, const float* __restrict__ pq,
    const float* __restrict__ g, const float* __restrict__ be,
    float* __restrict__ scale, float* __restrict__ shift)
{
    int b = blockIdx.x;
    int c = threadIdx.x;
    float s = 0.f, q = 0.f;
    for (int j = 0; j < NCHUNK; j++) {
        size_t o = ((size_t)b * NCHUNK + j) * HD + c;
        s += ps[o];
        q += pq[o];
    }
    float mean = s * (1.0f / NN);
    float var  = fmaxf(q * (1.0f / NN) - mean * mean, 0.f);
    float sc   = g[b * HD + c] * rsqrtf(var + 1e-5f);
    scale[b * HD + c] = sc;
    shift[b * HD + c] = be[b * HD + c] - mean * sc;
}

// BN + relu + per-row max + quantize (layer 1 path)
__global__ __launch_bounds__(128) void bn1_quant(
    const float* __restrict__ hf, const float* __restrict__ scale,
    const float* __restrict__ shift,
    int8_t* __restrict__ q0, int8_t* __restrict__ q1, float* __restrict__ sa)
{
    __shared__ float wmx[4];
    int idx = blockIdx.x;            // b*NN + n
    int b = idx / NN;
    int t = threadIdx.x;
    int c = t * 4;
    float4 v   = *(const float4*)(hf + (size_t)idx * HD + c);
    float4 scv = *(const float4*)(scale + b * HD + c);
    float4 shv = *(const float4*)(shift + b * HD + c);
    float r0 = fmaxf(v.x * scv.x + shv.x, 0.f);
    float r1 = fmaxf(v.y * scv.y + shv.y, 0.f);
    float r2 = fmaxf(v.z * scv.z + shv.z, 0.f);
    float r3 = fmaxf(v.w * scv.w + shv.w, 0.f);
    float m = fmaxf(fmaxf(r0, r1), fmaxf(r2, r3));
#pragma unroll
    for (int off = 16; off >= 1; off >>= 1)
        m = fmaxf(m, __shfl_xor_sync(0xFFFFFFFFu, m, off));
    if ((t & 31) == 0) wmx[t >> 5] = m;
    __syncthreads();
    m = fmaxf(fmaxf(wmx[0], wmx[1]), fmaxf(wmx[2], wmx[3]));
    float s = fmaxf(m, 1e-20f) * (1.0f / 16256.0f);
    if (t == 0) sa[idx] = s;
    float inv = 1.0f / s;
    int a0, a1, b0q, b1q, c0q, c1q, d0q, d1q;
    q2(r0, inv, a0, a1); q2(r1, inv, b0q, b1q);
    q2(r2, inv, c0q, c1q); q2(r3, inv, d0q, d1q);
    size_t o = (size_t)idx * HD + c;
    *(char4*)(q0 + o) = make_char4(a0, b0q, c0q, d0q);
    *(char4*)(q1 + o) = make_char4(a1, b1q, c1q, d1q);
}

// layer2: per-(b,n) rowmax of BN'd relu'd values
__global__ __launch_bounds__(128) void bn2_rowmax(
    const float* __restrict__ hf, const float* __restrict__ scale,
    const float* __restrict__ shift, float* __restrict__ pmax)
{
    __shared__ float wmx[4];
    int idx = blockIdx.x;
    int b = idx / NN;
    int t = threadIdx.x;
    int c = t * 4;
    float4 v   = *(const float4*)(hf + (size_t)idx * HD + c);
    float4 scv = *(const float4*)(scale + b * HD + c);
    float4 shv = *(const float4*)(shift + b * HD + c);
    float r0 = fmaxf(v.x * scv.x + shv.x, 0.f);
    float r1 = fmaxf(v.y * scv.y + shv.y, 0.f);
    float r2 = fmaxf(v.z * scv.z + shv.z, 0.f);
    float r3 = fmaxf(v.w * scv.w + shv.w, 0.f);
    float m = fmaxf(fmaxf(r0, r1), fmaxf(r2, r3));
#pragma unroll
    for (int off = 16; off >= 1; off >>= 1)
        m = fmaxf(m, __shfl_xor_sync(0xFFFFFFFFu, m, off));
    if ((t & 31) == 0) wmx[t >> 5] = m;
    __syncthreads();
    if (t == 0)
        pmax[idx] = fmaxf(fmaxf(wmx[0], wmx[1]), fmaxf(wmx[2], wmx[3]));
}

// s3[n] = global scale across branches
__global__ __launch_bounds__(256) void s3_red(
    const float* __restrict__ pmax, float* __restrict__ s3)
{
    int n = blockIdx.x * 256 + threadIdx.x;
    if (n >= NN) return;
    float m = 0.f;
#pragma unroll
    for (int b = 0; b < BB; b++) m = fmaxf(m, pmax[b * NN + n]);
    s3[n] = fmaxf(m, 1e-20f) * (1.0f / 16256.0f);
}

// layer2: BN + relu + quantize with node-global scale s3[n]
__global__ __launch_bounds__(128) void bn2_quant(
    const float* __restrict__ hf, const float* __restrict__ scale,
    const float* __restrict__ shift, const float* __restrict__ s3,
    int8_t* __restrict__ q0, int8_t* __restrict__ q1)
{
    int idx = blockIdx.x;
    int b = idx / NN;
    int n = idx - b * NN;
    int t = threadIdx.x;
    int c = t * 4;
    float4 v   = *(const float4*)(hf + (size_t)idx * HD + c);
    float4 scv = *(const float4*)(scale + b * HD + c);
    float4 shv = *(const float4*)(shift + b * HD + c);
    float r0 = fmaxf(v.x * scv.x + shv.x, 0.f);
    float r1 = fmaxf(v.y * scv.y + shv.y, 0.f);
    float r2 = fmaxf(v.z * scv.z + shv.z, 0.f);
    float r3 = fmaxf(v.w * scv.w + shv.w, 0.f);
    float inv = 1.0f / s3[n];
    int a0, a1, b0q, b1q, c0q, c1q, d0q, d1q;
    q2(r0, inv, a0, a1); q2(r1, inv, b0q, b1q);
    q2(r2, inv, c0q, c1q); q2(r3, inv, d0q, d1q);
    size_t o = (size_t)idx * HD + c;
    *(char4*)(q0 + o) = make_char4(a0, b0q, c0q, d0q);
    *(char4*)(q1 + o) = make_char4(a1, b1q, c1q, d1q);
}

// =================================================================
// KAN (unchanged, validated)
// =================================================================
__device__ __forceinline__ void kan_bases(float x, float* out9)
{
    out9[0] = x / (1.0f + expf(-x));
    float b[11];
#pragma unroll
    for (int j = 0; j < 11; j++) {
        float gj  = (float)(j - 3) * 0.4f - 1.0f;
        float gj1 = (float)(j - 2) * 0.4f - 1.0f;
        b[j] = (x >= gj && x < gj1) ? 1.0f : 0.0f;
    }
#pragma unroll
    for (int p = 1; p <= 3; p++) {
        float inv = 1.0f / (0.4f * (float)p);
#pragma unroll
        for (int j = 0; j < 10; j++) {
            if (j < 11 - p) {
                float gj   = (float)(j - 3) * 0.4f - 1.0f;
                float gjp1 = (float)(j + p - 2) * 0.4f - 1.0f;
                b[j] = (x - gj) * inv * b[j] + (gjp1 - x) * inv * b[j + 1];
            }
        }
    }
#pragma unroll
    for (int j = 0; j < 8; j++) out9[1 + j] = b[j];
}

__global__ __launch_bounds__(256) void kan1_prep(
    const float* __restrict__ bw1, const float* __restrict__ sw1,
    const float* __restrict__ sc1, float* __restrict__ wAll)
{
    int idx = blockIdx.x * 256 + threadIdx.x;
    if (idx >= F1 * 9 * 32) return;
    int o = idx & 31;
    int t = idx >> 5;
    int c = t % 9;
    int i = t / 9;
    wAll[idx] = (c == 0) ? bw1[o * F1 + i]
                         : sw1[(o * F1 + i) * 8 + (c - 1)] * sc1[o * F1 + i];
}

__global__ __launch_bounds__(256) void kan1_kernel(
    const float* __restrict__ f, const float* __restrict__ wAll, float* __restrict__ f2)
{
    __shared__ float xs[32][16];
    __shared__ float augS[16 * 9][32];
    __shared__ float wS[16 * 9][32];

    int tid = threadIdx.x;
    int n0  = blockIdx.x * 32;
    int tx  = tid & 15;
    int ty  = tid >> 4;

    float a00 = 0.f, a01 = 0.f, a10 = 0.f, a11 = 0.f;

    for (int i0 = 0; i0 < F1; i0 += 16) {
        __syncthreads();
        if (tid < 128) {
            int r  = tid >> 2;
            int c4 = (tid & 3) * 4;
            *(float4*)&xs[r][c4] =
                *(const float4*)(f + (size_t)(n0 + r) * F1 + i0 + c4);
        }
        {
            const float4* src = (const float4*)(wAll + (size_t)i0 * 9 * 32);
            float4* dst = (float4*)&wS[0][0];
            for (int q = tid; q < (16 * 9 * 32) / 4; q += 256) dst[q] = src[q];
        }
        __syncthreads();
#pragma unroll
        for (int j = 0; j < 2; j++) {
            int p  = tid + j * 256;
            int r  = p & 31;
            int ci = p >> 5;
            float out9[9];
            kan_bases(xs[r][ci], out9);
#pragma unroll
            for (int c = 0; c < 9; c++) augS[ci * 9 + c][r] = out9[c];
        }
        __syncthreads();
#pragma unroll 4
        for (int kk = 0; kk < 16 * 9; kk++) {
            float x0 = augS[kk][ty], x1 = augS[kk][ty + 16];
            float w0 = wS[kk][tx],   w1 = wS[kk][tx + 16];
            a00 += x0 * w0; a01 += x0 * w1;
            a10 += x1 * w0; a11 += x1 * w1;
        }
    }

    f2[(size_t)(n0 + ty) * 32 + tx]           = a00;
    f2[(size_t)(n0 + ty) * 32 + tx + 16]      = a01;
    f2[(size_t)(n0 + ty + 16) * 32 + tx]      = a10;
    f2[(size_t)(n0 + ty + 16) * 32 + tx + 16] = a11;
}

__global__ __launch_bounds__(256) void kan2_kernel(
    const float* __restrict__ f2,
    const float* __restrict__ bw2, const float* __restrict__ sw2,
    const float* __restrict__ sc2, float* __restrict__ out)
{
    __shared__ float wS[10 * 32 * 9];
    for (int q = threadIdx.x; q < 10 * 32 * 9; q += 256) {
        int o = q / 288;
        int r = q % 288;
        int i = r / 9;
        int c = r % 9;
        wS[q] = (c == 0) ? bw2[o * 32 + i]
                         : sw2[(o * 32 + i) * 8 + (c - 1)] * sc2[o * 32 + i];
    }
    __syncthreads();

    int n = blockIdx.x * 256 + threadIdx.x;
    if (n >= NN) return;

    float xin[32];
#pragma unroll
    for (int q = 0; q < 8; q++)
        *(float4*)&xin[q * 4] = *(const float4*)(f2 + (size_t)n * 32 + q * 4);

    float acc[10];
#pragma unroll
    for (int o = 0; o < 10; o++) acc[o] = 0.f;

    for (int i = 0; i < 32; i++) {
        float out9[9];
        kan_bases(xin[i], out9);
#pragma unroll
        for (int o = 0; o < 10; o++) {
            const float* w = &wS[o * 288 + i * 9];
#pragma unroll
            for (int c = 0; c < 9; c++) acc[o] += out9[c] * w[c];
        }
    }
#pragma unroll
    for (int o = 0; o < 10; o++) out[(size_t)n * 10 + o] = acc[o];
}

// =================================================================
// launch
// =================================================================
extern "C" void kernel_launch(void* const* d_in, const int* in_sizes, int n_in,
                              void* d_out, int out_size)
{
    const float* x   = (const float*)d_in[0];
    const float* W1  = (const float*)d_in[3];
    const float* b1  = (const float*)d_in[4];
    const float* g1  = (const float*)d_in[5];
    const float* be1 = (const float*)d_in[6];
    const float* W2  = (const float*)d_in[7];
    const float* b2  = (const float*)d_in[8];
    const float* g2  = (const float*)d_in[9];
    const float* be2 = (const float*)d_in[10];
    const float* Wf  = (const float*)d_in[11];
    const float* bf  = (const float*)d_in[12];
    const float* bw1 = (const float*)d_in[13];
    const float* sw1 = (const float*)d_in[14];
    const float* sc1 = (const float*)d_in[15];
    const float* bw2 = (const float*)d_in[16];
    const float* sw2 = (const float*)d_in[17];
    const float* sc2 = (const float*)d_in[18];
    float* out = (float*)d_out;

    float *hfp, *fp, *f2p, *psp, *pqp, *scp, *shp, *wallp;
    float *sxa, *sh1, *s3, *pmax, *sw1p, *sw2p, *swfp, *pwp;
    int8_t *xq0, *xq1, *h1q0, *h1q1, *h2q0, *h2q1;
    int8_t *w1q0, *w1q1, *w2q0, *w2q1, *wfq0, *wfq1;
    cudaGetSymbolAddress((void**)&hfp,  d_hf);
    cudaGetSymbolAddress((void**)&fp,   d_f);
    cudaGetSymbolAddress((void**)&f2p,  d_f2);
    cudaGetSymbolAddress((void**)&psp,  d_ps);
    cudaGetSymbolAddress((void**)&pqp,  d_pq);
    cudaGetSymbolAddress((void**)&scp,  d_scale);
    cudaGetSymbolAddress((void**)&shp,  d_shift);
    cudaGetSymbolAddress((void**)&wallp,d_wall);
    cudaGetSymbolAddress((void**)&sxa,  d_sxa);
    cudaGetSymbolAddress((void**)&sh1,  d_sh1);
    cudaGetSymbolAddress((void**)&s3,   d_s3);
    cudaGetSymbolAddress((void**)&pmax, d_pmax);
    cudaGetSymbolAddress((void**)&sw1p, d_sw1);
    cudaGetSymbolAddress((void**)&sw2p, d_sw2);
    cudaGetSymbolAddress((void**)&swfp, d_swf);
    cudaGetSymbolAddress((void**)&pwp,  d_pw);
    cudaGetSymbolAddress((void**)&xq0,  d_xq0);
    cudaGetSymbolAddress((void**)&xq1,  d_xq1);
    cudaGetSymbolAddress((void**)&h1q0, d_h1q0);
    cudaGetSymbolAddress((void**)&h1q1, d_h1q1);
    cudaGetSymbolAddress((void**)&h2q0, d_h2q0);
    cudaGetSymbolAddress((void**)&h2q1, d_h2q1);
    cudaGetSymbolAddress((void**)&w1q0, d_w1q0);
    cudaGetSymbolAddress((void**)&w1q1, d_w1q1);
    cudaGetSymbolAddress((void**)&w2q0, d_w2q0);
    cudaGetSymbolAddress((void**)&w2q1, d_w2q1);
    cudaGetSymbolAddress((void**)&wfq0, d_wfq0);
    cudaGetSymbolAddress((void**)&wfq1, d_wfq1);

    cudaFuncSetAttribute(gemm_i8<false, false>,
                         cudaFuncAttributeMaxDynamicSharedMemorySize, IDYN);
    cudaFuncSetAttribute(gemm_i8<true, true>,
                         cudaFuncAttributeMaxDynamicSharedMemorySize, IDYN);

    // ---- weight + x quant prep ----
    wmax_part<<<dim3(HD / 256, BB, 8), 256>>>(W1, pwp, FEAT, HD);
    wmax_red<<<(BB * HD + 255) / 256, 256>>>(pwp, sw1p, BB * HD);
    tquant<<<dim3(HD / 32, FEAT / 32, BB), 256>>>(W1, sw1p, w1q0, w1q1, FEAT, HD);
    wmax_part<<<dim3(HD / 256, BB, 8), 256>>>(W2, pwp, HD, HD);
    wmax_red<<<(BB * HD + 255) / 256, 256>>>(pwp, sw2p, BB * HD);
    tquant<<<dim3(HD / 32, HD / 32, BB), 256>>>(W2, sw2p, w2q0, w2q1, HD, HD);
    wmax_part<<<dim3(F1 / 256, 1, 8), 256>>>(Wf, pwp, CATK, F1);
    wmax_red<<<(F1 + 255) / 256, 256>>>(pwp, swfp, F1);
    tquant<<<dim3(F1 / 32, CATK / 32, 1), 256>>>(Wf, swfp, wfq0, wfq1, CATK, F1);
    xquant<<<BB * NN / 8, 256>>>(x, xq0, xq1, sxa);
    kan1_prep<<<(F1 * 9 * 32 + 255) / 256, 256>>>(bw1, sw1, sc1, wallp);

    dim3 g12(HD / 64, (NN + 127) / 128, BB);   // (8, 157, 8)
    dim3 g3(F1 / 64, (NN + 127) / 128, 1);     // (16, 157, 1)
    dim3 bn_grid(NCHUNK, BB);

    // layer 1
    gemm_i8<false, false><<<g12, 256, IDYN>>>(xq0, xq1, sxa, w1q0, w1q1, sw1p,
                                              b1, hfp, NN, HD, FEAT);
    bn_partial<<<bn_grid, 256>>>(hfp, psp, pqp);
    bn_finalize<<<BB, 512>>>(psp, pqp, g1, be1, scp, shp);
    bn1_quant<<<BB * NN, 128>>>(hfp, scp, shp, h1q0, h1q1, sh1);

    // layer 2
    gemm_i8<false, false><<<g12, 256, IDYN>>>(h1q0, h1q1, sh1, w2q0, w2q1, sw2p,
                                              b2, hfp, NN, HD, HD);
    bn_partial<<<bn_grid, 256>>>(hfp, psp, pqp);
    bn_finalize<<<BB, 512>>>(psp, pqp, g2, be2, scp, shp);
    bn2_rowmax<<<BB * NN, 128>>>(hfp, scp, shp, pmax);
    s3_red<<<(NN + 255) / 256, 256>>>(pmax, s3);
    bn2_quant<<<BB * NN, 128>>>(hfp, scp, shp, s3, h2q0, h2q1);

    // feature layer (concat folded into A-gather)
    gemm_i8<true, true><<<g3, 256, IDYN>>>(h2q0, h2q1, s3, wfq0, wfq1, swfp,
                                           bf, fp, NN, F1, CATK);

    // KAN
    kan1_kernel<<<NN / 32, 256>>>(fp, wallp, f2p);
    kan2_kernel<<<(NN + 255) / 256, 256>>>(f2p, bw2, sw2, sc2, out);
}